// round 1
// baseline (speedup 1.0000x reference)
#include <cuda_runtime.h>
#include <math.h>

// ---------------------------------------------------------------------------
// Problem constants (hardcoded from reference setup_inputs: B=8, N=5376,
// Cin=384, Ch=768, H=W=32, n=N/21=256)
// ---------------------------------------------------------------------------
#define BB      8
#define NTOK    5376
#define CIN     384
#define CH      768
#define MROWS   (BB * NTOK)          // 43008

// token segments: [0,4096) -> 64x64, [4096,5120) -> 32x32, [5120,5376) -> 16x16

// ---------------------------------------------------------------------------
// Scratch (device globals; no runtime allocation)
// ---------------------------------------------------------------------------
__device__ float g_h1[(size_t)MROWS * CH];     // fc1 output
__device__ float g_hc[(size_t)MROWS * CH];     // dwconv output, later gelu'd in place
__device__ float g_avg[24 * CH];               // (scale*8 + b, c)
__device__ float g_max[24 * CH];
__device__ float g_scale[24 * CH];

// ---------------------------------------------------------------------------
// SGEMM body: C[M,N] = A[M,K] @ W[K,N] + bias[N]
// BM=BN=128, BK=16, 256 threads, 8x8 per thread.
// M % 128 == 0, N % 128 == 0, K % 16 == 0 for all calls here.
// ---------------------------------------------------------------------------
__device__ __forceinline__ void sgemm_body(
    const float* __restrict__ A, const float* __restrict__ W,
    const float* __restrict__ bias, float* __restrict__ C,
    int M, int N, int K)
{
    constexpr int BK = 16;
    __shared__ float As[BK][128];   // stored k-major (transposed)
    __shared__ float Bs[BK][128];

    const int tid  = threadIdx.x;
    const int brow = blockIdx.y * 128;
    const int bcol = blockIdx.x * 128;
    const int tx   = tid & 15;
    const int ty   = tid >> 4;

    float acc[8][8];
#pragma unroll
    for (int i = 0; i < 8; i++)
#pragma unroll
        for (int j = 0; j < 8; j++) acc[i][j] = 0.0f;

    for (int k0 = 0; k0 < K; k0 += BK) {
        // Load A tile: 128 rows x 16 k = 2048 floats = 512 float4 (2/thread)
#pragma unroll
        for (int u = 0; u < 2; u++) {
            int li = tid + u * 256;
            int ar = li >> 2;            // 0..127
            int ac = (li & 3) * 4;       // 0,4,8,12
            float4 v = *(const float4*)(A + (size_t)(brow + ar) * K + k0 + ac);
            As[ac + 0][ar] = v.x;
            As[ac + 1][ar] = v.y;
            As[ac + 2][ar] = v.z;
            As[ac + 3][ar] = v.w;
        }
        // Load B tile: 16 k x 128 cols = 512 float4 (2/thread)
#pragma unroll
        for (int u = 0; u < 2; u++) {
            int li = tid + u * 256;
            int kr = li >> 5;            // 0..15
            int wc = (li & 31) * 4;      // 0..124
            *(float4*)(&Bs[kr][wc]) =
                *(const float4*)(W + (size_t)(k0 + kr) * N + bcol + wc);
        }
        __syncthreads();

#pragma unroll
        for (int kk = 0; kk < BK; kk++) {
            float a[8], bv[8];
#pragma unroll
            for (int i = 0; i < 8; i++) a[i]  = As[kk][ty * 8 + i];
#pragma unroll
            for (int j = 0; j < 8; j++) bv[j] = Bs[kk][tx * 8 + j];
#pragma unroll
            for (int i = 0; i < 8; i++)
#pragma unroll
                for (int j = 0; j < 8; j++)
                    acc[i][j] += a[i] * bv[j];
        }
        __syncthreads();
    }

#pragma unroll
    for (int i = 0; i < 8; i++) {
        int row = brow + ty * 8 + i;
#pragma unroll
        for (int j = 0; j < 8; j += 4) {
            int col = bcol + tx * 8 + j;
            float4 o;
            o.x = acc[i][j + 0] + bias[col + 0];
            o.y = acc[i][j + 1] + bias[col + 1];
            o.z = acc[i][j + 2] + bias[col + 2];
            o.w = acc[i][j + 3] + bias[col + 3];
            *(float4*)(C + (size_t)row * N + col) = o;
        }
    }
}

__global__ void __launch_bounds__(256)
fc1_kernel(const float* __restrict__ x, const float* __restrict__ w,
           const float* __restrict__ b)
{
    sgemm_body(x, w, b, g_h1, MROWS, CH, CIN);
}

__global__ void __launch_bounds__(256)
fc2_kernel(const float* __restrict__ w, const float* __restrict__ b,
           float* __restrict__ out)
{
    sgemm_body(g_hc, w, b, out, MROWS, CIN, CH);
}

// ---------------------------------------------------------------------------
// Depthwise 3x3 conv (SAME, per-channel) + per-(scale,b,c) sum & max.
// Block = 32 channels x 8 token-slots. Grid = (24 channel chunks, 8 B, 3 scales)
// Input/output layout: token-major (row = b*5376 + off + tok, col = c) so the
// 32 channel lanes of a warp hit one contiguous 128B line per tap.
// ---------------------------------------------------------------------------
__global__ void __launch_bounds__(256)
dwconv_kernel(const float* __restrict__ dw_w, const float* __restrict__ dw_b)
{
    const int s  = blockIdx.z;
    const int b  = blockIdx.y;
    const int cc = blockIdx.x;

    const int offs[3] = {0, 4096, 5120};
    const int lws[3]  = {6, 5, 4};
    const int off = offs[s];
    const int lw  = lws[s];
    const int w   = 1 << lw;
    const int ntok = w * w;

    const int tid   = threadIdx.x;
    const int c     = cc * 32 + (tid & 31);
    const int tslot = tid >> 5;

    float wgt[9];
#pragma unroll
    for (int i = 0; i < 9; i++) wgt[i] = dw_w[c * 9 + i];
    const float bk = dw_b[c];

    const float* base  = g_h1 + ((size_t)(b * NTOK + off)) * CH + c;
    float*       obase = g_hc + ((size_t)(b * NTOK + off)) * CH + c;

    float lsum = 0.0f;
    float lmax = -INFINITY;

    for (int tok = tslot; tok < ntok; tok += 8) {
        const int y = tok >> lw;
        const int x = tok & (w - 1);
        float acc = bk;
#pragma unroll
        for (int ky = 0; ky < 3; ky++) {
            const int yy = y + ky - 1;
            if ((unsigned)yy < (unsigned)w) {
                const int rb = yy << lw;
#pragma unroll
                for (int kx = 0; kx < 3; kx++) {
                    const int xx = x + kx - 1;
                    if ((unsigned)xx < (unsigned)w)
                        acc += wgt[ky * 3 + kx] * base[(size_t)(rb + xx) * CH];
                }
            }
        }
        obase[(size_t)tok * CH] = acc;
        lsum += acc;
        lmax = fmaxf(lmax, acc);
    }

    __shared__ float ssum[256];
    __shared__ float smax[256];
    ssum[tid] = lsum;
    smax[tid] = lmax;
    __syncthreads();
    if (tslot == 0) {
        float ts = lsum, tm = lmax;
#pragma unroll
        for (int j = 1; j < 8; j++) {
            ts += ssum[j * 32 + tid];
            tm = fmaxf(tm, smax[j * 32 + tid]);
        }
        const int sb = s * 8 + b;
        g_avg[sb * CH + c] = ts / (float)ntok;
        g_max[sb * CH + c] = tm;
    }
}

// ---------------------------------------------------------------------------
// Gate softmax + channel-conv1 SE gates -> per-(scale,b,c) scale factor.
// One block per (scale,b) pair (24 blocks).
// ---------------------------------------------------------------------------
__global__ void __launch_bounds__(256)
gate_scale_kernel(const float* __restrict__ gate_w, const float* __restrict__ gate_b,
                  const float* __restrict__ ca_w,   const float* __restrict__ ra_w)
{
    const int sb  = blockIdx.x;   // s*8 + b
    const int tid = threadIdx.x;

    __shared__ float pool[CH + 2];
    __shared__ float red0[256];
    __shared__ float red1[256];
    __shared__ float gw0s, gw1s;

    float d0 = 0.0f, d1 = 0.0f;
    for (int c = tid; c < CH; c += 256) {
        const float a = g_avg[sb * CH + c];
        const float m = g_max[sb * CH + c];
        pool[c + 1] = a + m;
        d0 += a * gate_w[c * 2 + 0];
        d1 += a * gate_w[c * 2 + 1];
    }
    if (tid == 0) { pool[0] = 0.0f; pool[CH + 1] = 0.0f; }
    red0[tid] = d0;
    red1[tid] = d1;
    __syncthreads();
    for (int sft = 128; sft > 0; sft >>= 1) {
        if (tid < sft) {
            red0[tid] += red0[tid + sft];
            red1[tid] += red1[tid + sft];
        }
        __syncthreads();
    }
    if (tid == 0) {
        const float l0 = red0[0] + gate_b[0];
        const float l1 = red1[0] + gate_b[1];
        const float m  = fmaxf(l0, l1);
        const float e0 = expf(l0 - m), e1 = expf(l1 - m);
        const float inv = 1.0f / (e0 + e1);
        gw0s = e0 * inv;
        gw1s = e1 * inv;
    }
    __syncthreads();

    const float c0 = ca_w[0], c1 = ca_w[1], c2 = ca_w[2];
    const float r0 = ra_w[0], r1 = ra_w[1], r2 = ra_w[2];
    const float gw0 = gw0s, gw1 = gw1s;
    for (int c = tid; c < CH; c += 256) {
        const float pm = pool[c], pc = pool[c + 1], pp = pool[c + 2];
        const float cav = c0 * pm + c1 * pc + c2 * pp;
        const float rav = r0 * pm + r1 * pc + r2 * pp;
        const float cas = 1.0f / (1.0f + expf(-cav));
        const float ras = 1.0f - 1.0f / (1.0f + expf(-rav));
        g_scale[sb * CH + c] = gw0 * cas + gw1 * ras;
    }
}

// ---------------------------------------------------------------------------
// Elementwise: g_hc <- gelu_exact(g_hc * scale[sb, c])  (in place, float4)
// ---------------------------------------------------------------------------
__device__ __forceinline__ float gelu_exact(float v)
{
    return 0.5f * v * (1.0f + erff(v * 0.70710678118654752440f));
}

__global__ void __launch_bounds__(256)
gelu_scale_kernel()
{
    const size_t nvec = (size_t)MROWS * CH / 4;
    const size_t i = (size_t)blockIdx.x * blockDim.x + threadIdx.x;
    if (i >= nvec) return;
    const size_t e   = i * 4;
    const int    row = (int)(e / CH);
    const int    c   = (int)(e % CH);
    const int    b   = row / NTOK;
    const int    tok = row % NTOK;
    const int    s   = (tok < 4096) ? 0 : ((tok < 5120) ? 1 : 2);

    float4 v  = *(const float4*)(g_hc + e);
    float4 sc = *(const float4*)(g_scale + (s * 8 + b) * CH + c);
    v.x = gelu_exact(v.x * sc.x);
    v.y = gelu_exact(v.y * sc.y);
    v.z = gelu_exact(v.z * sc.z);
    v.w = gelu_exact(v.w * sc.w);
    *(float4*)(g_hc + e) = v;
}

// ---------------------------------------------------------------------------
// Entry point
// ---------------------------------------------------------------------------
extern "C" void kernel_launch(void* const* d_in, const int* in_sizes, int n_in,
                              void* d_out, int out_size)
{
    const float* x      = (const float*)d_in[0];
    const float* fc1_w  = (const float*)d_in[1];
    const float* fc1_b  = (const float*)d_in[2];
    const float* dw_w   = (const float*)d_in[3];
    const float* dw_b   = (const float*)d_in[4];
    const float* ca_w   = (const float*)d_in[5];
    const float* ra_w   = (const float*)d_in[6];
    const float* gate_w = (const float*)d_in[7];
    const float* gate_b = (const float*)d_in[8];
    const float* fc2_w  = (const float*)d_in[9];
    const float* fc2_b  = (const float*)d_in[10];
    float* out = (float*)d_out;

    // fc1: (43008 x 384) @ (384 x 768) -> g_h1
    fc1_kernel<<<dim3(CH / 128, MROWS / 128), 256>>>(x, fc1_w, fc1_b);

    // depthwise conv + pooled stats
    dwconv_kernel<<<dim3(CH / 32, BB, 3), 256>>>(dw_w, dw_b);

    // gate softmax + SE channel gates
    gate_scale_kernel<<<24, 256>>>(gate_w, gate_b, ca_w, ra_w);

    // scale + exact GELU (in place on g_hc)
    const int nvec = MROWS * CH / 4;
    gelu_scale_kernel<<<(nvec + 255) / 256, 256>>>();

    // fc2: (43008 x 768) @ (768 x 384) + bias -> out
    fc2_kernel<<<dim3(CIN / 128, MROWS / 128), 256>>>(fc2_w, fc2_b, out);
}

// round 2
// speedup vs baseline: 2.0068x; 2.0068x over previous
#include <cuda_runtime.h>
#include <math.h>
#include <stdint.h>

// ---------------------------------------------------------------------------
// Problem constants (B=8, N=5376, Cin=384, Ch=768, H=W=32, n=256)
// ---------------------------------------------------------------------------
#define BB      8
#define NTOK    5376
#define CIN     384
#define CH      768
#define MROWS   (BB * NTOK)          // 43008

// ---------------------------------------------------------------------------
// Scratch
// ---------------------------------------------------------------------------
__device__ float g_h1[(size_t)MROWS * CH];
__device__ float g_hc[(size_t)MROWS * CH];
__device__ float g_avg[24 * CH];
__device__ float g_max[24 * CH];
__device__ float g_scale[24 * CH];

// ---------------------------------------------------------------------------
// TF32 tensor-core GEMM: C[M,N] = A[M,K] @ W[K,N] + bias[N]
// BM=BN=128, BK=16, 256 threads (8 warps), warp tile 32x64,
// mma.sync.m16n8k8.tf32, 2-stage cp.async pipeline.
// Requires M%128==0, N%128==0, K%16==0.
// ---------------------------------------------------------------------------
#define BM 128
#define BN 128
#define BK 16
#define AROW 20     // As padded row (floats): banks (4g+tig) -> conflict-free
#define BROW 136    // Bs padded row (floats): banks (8tig+g) -> conflict-free

__device__ __forceinline__ uint32_t f2tf32(float x) {
    uint32_t y;
    asm("cvt.rna.tf32.f32 %0, %1;" : "=r"(y) : "f"(x));
    return y;
}
__device__ __forceinline__ void cp16(uint32_t d, const void* s) {
    asm volatile("cp.async.cg.shared.global [%0], [%1], 16;\n" :: "r"(d), "l"(s));
}
__device__ __forceinline__ void cp_commit() {
    asm volatile("cp.async.commit_group;\n" ::: "memory");
}
__device__ __forceinline__ void cp_wait1() {
    asm volatile("cp.async.wait_group 1;\n" ::: "memory");
}
__device__ __forceinline__ void mma_tf32(float& d0, float& d1, float& d2, float& d3,
                                         uint32_t a0, uint32_t a1, uint32_t a2, uint32_t a3,
                                         uint32_t b0, uint32_t b1) {
    asm volatile(
        "mma.sync.aligned.m16n8k8.row.col.f32.tf32.tf32.f32 "
        "{%0,%1,%2,%3}, {%4,%5,%6,%7}, {%8,%9}, {%0,%1,%2,%3};\n"
        : "+f"(d0), "+f"(d1), "+f"(d2), "+f"(d3)
        : "r"(a0), "r"(a1), "r"(a2), "r"(a3), "r"(b0), "r"(b1));
}

__global__ void __launch_bounds__(256, 2)
gemm_tf32(const float* __restrict__ A, const float* __restrict__ W,
          const float* __restrict__ bias, float* __restrict__ C,
          int N, int K)
{
    __shared__ float As[2][BM][AROW];
    __shared__ float Bs[2][BK][BROW];

    const int tid  = threadIdx.x;
    const int brow = blockIdx.y * BM;
    const int bcol = blockIdx.x * BN;

    const int lane = tid & 31;
    const int wid  = tid >> 5;
    const int g    = lane >> 2;    // group id 0..7
    const int tig  = lane & 3;     // thread in group 0..3
    const int wm   = wid & 3;      // warp m 0..3 (32 rows each)
    const int wn   = wid >> 2;     // warp n 0..1 (64 cols each)

    const uint32_t asBase = (uint32_t)__cvta_generic_to_shared(&As[0][0][0]);
    const uint32_t bsBase = (uint32_t)__cvta_generic_to_shared(&Bs[0][0][0]);

    // Load-index decomposition (coalesced):
    const int ar  = tid >> 2;        // A rows (+64 on second pass)
    const int ac4 = (tid & 3) * 4;   // A col within BK
    const int br  = tid >> 5;        // B rows (+8 on second pass)
    const int bc4 = (tid & 31) * 4;  // B col within BN

    float acc[2][8][4];
#pragma unroll
    for (int mt = 0; mt < 2; mt++)
#pragma unroll
        for (int nt = 0; nt < 8; nt++)
#pragma unroll
            for (int v = 0; v < 4; v++) acc[mt][nt][v] = 0.0f;

    const int KT = K / BK;

    // ---- stage loader ----
    auto load_stage = [&](int st, int kt) {
#pragma unroll
        for (int u = 0; u < 2; u++) {
            const int row = ar + u * 64;
            const uint32_t dst = asBase + (uint32_t)(((st * BM + row) * AROW + ac4) * 4);
            cp16(dst, A + (size_t)(brow + row) * K + kt * BK + ac4);
        }
#pragma unroll
        for (int u = 0; u < 2; u++) {
            const int row = br + u * 8;
            const uint32_t dst = bsBase + (uint32_t)(((st * BK + row) * BROW + bc4) * 4);
            cp16(dst, W + (size_t)(kt * BK + row) * N + bcol + bc4);
        }
    };

    load_stage(0, 0); cp_commit();
    load_stage(1, 1); cp_commit();
    cp_wait1();
    __syncthreads();

    for (int kt = 0; kt < KT; kt++) {
        const int cur = kt & 1;

        // ---- compute current stage ----
#pragma unroll
        for (int kc = 0; kc < BK; kc += 8) {
            uint32_t af[2][4], bf[8][2];
#pragma unroll
            for (int mt = 0; mt < 2; mt++) {
                const int r0 = wm * 32 + mt * 16 + g;
                af[mt][0] = f2tf32(As[cur][r0    ][kc + tig    ]);
                af[mt][1] = f2tf32(As[cur][r0 + 8][kc + tig    ]);
                af[mt][2] = f2tf32(As[cur][r0    ][kc + tig + 4]);
                af[mt][3] = f2tf32(As[cur][r0 + 8][kc + tig + 4]);
            }
#pragma unroll
            for (int nt = 0; nt < 8; nt++) {
                const int c0 = wn * 64 + nt * 8 + g;
                bf[nt][0] = f2tf32(Bs[cur][kc + tig    ][c0]);
                bf[nt][1] = f2tf32(Bs[cur][kc + tig + 4][c0]);
            }
#pragma unroll
            for (int mt = 0; mt < 2; mt++)
#pragma unroll
                for (int nt = 0; nt < 8; nt++)
                    mma_tf32(acc[mt][nt][0], acc[mt][nt][1], acc[mt][nt][2], acc[mt][nt][3],
                             af[mt][0], af[mt][1], af[mt][2], af[mt][3],
                             bf[nt][0], bf[nt][1]);
        }

        __syncthreads();                 // all warps done reading 'cur'
        if (kt + 2 < KT) load_stage(cur, kt + 2);
        cp_commit();                     // empty group in tail keeps counting consistent
        cp_wait1();                      // stage (kt+1) now resident
        __syncthreads();
    }

    // ---- epilogue: bias + float2 stores ----
#pragma unroll
    for (int nt = 0; nt < 8; nt++) {
        const int col = bcol + wn * 64 + nt * 8 + 2 * tig;
        const float b0 = bias[col];
        const float b1 = bias[col + 1];
#pragma unroll
        for (int mt = 0; mt < 2; mt++) {
            const int row0 = brow + wm * 32 + mt * 16 + g;
            float2 o0 = make_float2(acc[mt][nt][0] + b0, acc[mt][nt][1] + b1);
            float2 o1 = make_float2(acc[mt][nt][2] + b0, acc[mt][nt][3] + b1);
            *(float2*)(C + (size_t)row0 * N + col)       = o0;
            *(float2*)(C + (size_t)(row0 + 8) * N + col) = o1;
        }
    }
}

// ---------------------------------------------------------------------------
// Depthwise 3x3 conv + per-(scale,b,c) sum & max  (unchanged from R1)
// ---------------------------------------------------------------------------
__global__ void __launch_bounds__(256)
dwconv_kernel(const float* __restrict__ dw_w, const float* __restrict__ dw_b)
{
    const int s  = blockIdx.z;
    const int b  = blockIdx.y;
    const int cc = blockIdx.x;

    const int offs[3] = {0, 4096, 5120};
    const int lws[3]  = {6, 5, 4};
    const int off = offs[s];
    const int lw  = lws[s];
    const int w   = 1 << lw;
    const int ntok = w * w;

    const int tid   = threadIdx.x;
    const int c     = cc * 32 + (tid & 31);
    const int tslot = tid >> 5;

    float wgt[9];
#pragma unroll
    for (int i = 0; i < 9; i++) wgt[i] = dw_w[c * 9 + i];
    const float bk = dw_b[c];

    const float* base  = g_h1 + ((size_t)(b * NTOK + off)) * CH + c;
    float*       obase = g_hc + ((size_t)(b * NTOK + off)) * CH + c;

    float lsum = 0.0f;
    float lmax = -INFINITY;

    for (int tok = tslot; tok < ntok; tok += 8) {
        const int y = tok >> lw;
        const int x = tok & (w - 1);
        float acc = bk;
#pragma unroll
        for (int ky = 0; ky < 3; ky++) {
            const int yy = y + ky - 1;
            if ((unsigned)yy < (unsigned)w) {
                const int rb = yy << lw;
#pragma unroll
                for (int kx = 0; kx < 3; kx++) {
                    const int xx = x + kx - 1;
                    if ((unsigned)xx < (unsigned)w)
                        acc += wgt[ky * 3 + kx] * base[(size_t)(rb + xx) * CH];
                }
            }
        }
        obase[(size_t)tok * CH] = acc;
        lsum += acc;
        lmax = fmaxf(lmax, acc);
    }

    __shared__ float ssum[256];
    __shared__ float smax[256];
    ssum[tid] = lsum;
    smax[tid] = lmax;
    __syncthreads();
    if (tslot == 0) {
        float ts = lsum, tm = lmax;
#pragma unroll
        for (int j = 1; j < 8; j++) {
            ts += ssum[j * 32 + tid];
            tm = fmaxf(tm, smax[j * 32 + tid]);
        }
        const int sb = s * 8 + b;
        g_avg[sb * CH + c] = ts / (float)ntok;
        g_max[sb * CH + c] = tm;
    }
}

// ---------------------------------------------------------------------------
// Gate softmax + SE channel gates -> per-(scale,b,c) scale (unchanged)
// ---------------------------------------------------------------------------
__global__ void __launch_bounds__(256)
gate_scale_kernel(const float* __restrict__ gate_w, const float* __restrict__ gate_b,
                  const float* __restrict__ ca_w,   const float* __restrict__ ra_w)
{
    const int sb  = blockIdx.x;
    const int tid = threadIdx.x;

    __shared__ float pool[CH + 2];
    __shared__ float red0[256];
    __shared__ float red1[256];
    __shared__ float gw0s, gw1s;

    float d0 = 0.0f, d1 = 0.0f;
    for (int c = tid; c < CH; c += 256) {
        const float a = g_avg[sb * CH + c];
        const float m = g_max[sb * CH + c];
        pool[c + 1] = a + m;
        d0 += a * gate_w[c * 2 + 0];
        d1 += a * gate_w[c * 2 + 1];
    }
    if (tid == 0) { pool[0] = 0.0f; pool[CH + 1] = 0.0f; }
    red0[tid] = d0;
    red1[tid] = d1;
    __syncthreads();
    for (int sft = 128; sft > 0; sft >>= 1) {
        if (tid < sft) {
            red0[tid] += red0[tid + sft];
            red1[tid] += red1[tid + sft];
        }
        __syncthreads();
    }
    if (tid == 0) {
        const float l0 = red0[0] + gate_b[0];
        const float l1 = red1[0] + gate_b[1];
        const float m  = fmaxf(l0, l1);
        const float e0 = expf(l0 - m), e1 = expf(l1 - m);
        const float inv = 1.0f / (e0 + e1);
        gw0s = e0 * inv;
        gw1s = e1 * inv;
    }
    __syncthreads();

    const float c0 = ca_w[0], c1 = ca_w[1], c2 = ca_w[2];
    const float r0 = ra_w[0], r1 = ra_w[1], r2 = ra_w[2];
    const float gw0 = gw0s, gw1 = gw1s;
    for (int c = tid; c < CH; c += 256) {
        const float pm = pool[c], pc = pool[c + 1], pp = pool[c + 2];
        const float cav = c0 * pm + c1 * pc + c2 * pp;
        const float rav = r0 * pm + r1 * pc + r2 * pp;
        const float cas = 1.0f / (1.0f + expf(-cav));
        const float ras = 1.0f - 1.0f / (1.0f + expf(-rav));
        g_scale[sb * CH + c] = gw0 * cas + gw1 * ras;
    }
}

// ---------------------------------------------------------------------------
// Elementwise: g_hc <- gelu_exact(g_hc * scale) (unchanged)
// ---------------------------------------------------------------------------
__device__ __forceinline__ float gelu_exact(float v)
{
    return 0.5f * v * (1.0f + erff(v * 0.70710678118654752440f));
}

__global__ void __launch_bounds__(256)
gelu_scale_kernel()
{
    const size_t nvec = (size_t)MROWS * CH / 4;
    const size_t i = (size_t)blockIdx.x * blockDim.x + threadIdx.x;
    if (i >= nvec) return;
    const size_t e   = i * 4;
    const int    row = (int)(e / CH);
    const int    c   = (int)(e % CH);
    const int    b   = row / NTOK;
    const int    tok = row % NTOK;
    const int    s   = (tok < 4096) ? 0 : ((tok < 5120) ? 1 : 2);

    float4 v  = *(const float4*)(g_hc + e);
    float4 sc = *(const float4*)(g_scale + (s * 8 + b) * CH + c);
    v.x = gelu_exact(v.x * sc.x);
    v.y = gelu_exact(v.y * sc.y);
    v.z = gelu_exact(v.z * sc.z);
    v.w = gelu_exact(v.w * sc.w);
    *(float4*)(g_hc + e) = v;
}

// ---------------------------------------------------------------------------
// Entry point
// ---------------------------------------------------------------------------
extern "C" void kernel_launch(void* const* d_in, const int* in_sizes, int n_in,
                              void* d_out, int out_size)
{
    const float* x      = (const float*)d_in[0];
    const float* fc1_w  = (const float*)d_in[1];
    const float* fc1_b  = (const float*)d_in[2];
    const float* dw_w   = (const float*)d_in[3];
    const float* dw_b   = (const float*)d_in[4];
    const float* ca_w   = (const float*)d_in[5];
    const float* ra_w   = (const float*)d_in[6];
    const float* gate_w = (const float*)d_in[7];
    const float* gate_b = (const float*)d_in[8];
    const float* fc2_w  = (const float*)d_in[9];
    const float* fc2_b  = (const float*)d_in[10];
    float* out = (float*)d_out;

    float* h1;
    cudaGetSymbolAddress((void**)&h1, g_h1);   // resolves device scratch (no alloc)
    float* hc;
    cudaGetSymbolAddress((void**)&hc, g_hc);

    // fc1: (43008 x 384) @ (384 x 768) -> g_h1
    gemm_tf32<<<dim3(CH / BN, MROWS / BM), 256>>>(x, fc1_w, fc1_b, h1, CH, CIN);

    // depthwise conv + pooled stats
    dwconv_kernel<<<dim3(CH / 32, BB, 3), 256>>>(dw_w, dw_b);

    // gate softmax + SE channel gates
    gate_scale_kernel<<<24, 256>>>(gate_w, gate_b, ca_w, ra_w);

    // scale + exact GELU (in place on g_hc)
    const int nvec = MROWS * CH / 4;
    gelu_scale_kernel<<<(nvec + 255) / 256, 256>>>();

    // fc2: (43008 x 768) @ (768 x 384) + bias -> out
    gemm_tf32<<<dim3(CIN / BN, MROWS / BM), 256>>>(hc, fc2_w, fc2_b, out, CIN, CH);
}